// round 1
// baseline (speedup 1.0000x reference)
#include <cuda_runtime.h>
#include <math.h>

#define PX 196
#define HS 14
#define SEQ 197
#define BIGL 1000000

__global__ __launch_bounds__(256) void blob_loss_kernel(
    const float* __restrict__ dot_qk,
    float* __restrict__ out,
    float inv_n)
{
    const int bh = blockIdx.x;
    const int t  = threadIdx.x;

    __shared__ float sx[PX];
    __shared__ float xv[PX];
    __shared__ float pu[PX];
    __shared__ int   lab[PX];
    __shared__ float red[256];
    __shared__ int   changed;
    __shared__ float s_mean, s_B;

    // ---- load: 196 contiguous floats at row 0, cols 1..196 of this (b,h) slab
    const float* rowp = dot_qk + (size_t)bh * (SEQ * SEQ) + 1;
    if (t < PX) sx[t] = rowp[t];
    __syncthreads();

    // ---- mean over 196
    float v = (t < PX) ? sx[t] : 0.0f;
    red[t] = v;
    __syncthreads();
    #pragma unroll
    for (int s = 128; s > 0; s >>= 1) {
        if (t < s) red[t] += red[t + s];
        __syncthreads();
    }
    if (t == 0) s_mean = red[0] * (1.0f / (float)PX);
    __syncthreads();
    const float m = s_mean;

    // ---- mask, xv, init labels
    bool  msk = false;
    float xvv = 0.0f;
    if (t < PX) {
        float x = sx[t];
        msk = (x > m);
        xvv = fmaxf(x - m, 0.0f) + 1e-9f;
        xv[t]  = xvv;
        lab[t] = msk ? t : BIGL;
        pu[t]  = 0.0f;
    }

    // ---- B = sum(xv over mask)
    red[t] = msk ? xvv : 0.0f;
    __syncthreads();
    #pragma unroll
    for (int s = 128; s > 0; s >>= 1) {
        if (t < s) red[t] += red[t + s];
        __syncthreads();
    }
    if (t == 0) s_B = red[0];

    // ---- connected components: min-propagation + pointer jumping to fixpoint
    const int ri = t / HS;
    const int ci = t - ri * HS;

    while (true) {
        __syncthreads();
        if (t == 0) changed = 0;
        __syncthreads();

        int newl = 0;
        if (msk) {
            newl = lab[t];
            #pragma unroll
            for (int di = -1; di <= 1; di++) {
                #pragma unroll
                for (int dj = -1; dj <= 1; dj++) {
                    int rr = ri + di, cc = ci + dj;
                    if (rr >= 0 && rr < HS && cc >= 0 && cc < HS) {
                        int l = lab[rr * HS + cc];
                        newl = min(newl, l);
                    }
                }
            }
            // pointer jumping (labels always index masked pixels; lab[l] <= l)
            newl = lab[newl];
            newl = lab[newl];
        }
        __syncthreads();
        if (msk && newl < lab[t]) {
            lab[t] = newl;
            changed = 1;
        }
        __syncthreads();
        if (!changed) break;
    }

    // ---- per-component sums via shared atomics
    if (msk) atomicAdd(&pu[lab[t]], xv[t]);
    __syncthreads();

    // ---- entropy over component roots
    float h = 0.0f;
    if (t < PX && msk && lab[t] == t) {
        float p = pu[t] / s_B;
        h = -p * logf(p);
    }
    red[t] = h;
    __syncthreads();
    #pragma unroll
    for (int s = 128; s > 0; s >>= 1) {
        if (t < s) red[t] += red[t + s];
        __syncthreads();
    }
    if (t == 0) atomicAdd(out, red[0] * inv_n);
}

extern "C" void kernel_launch(void* const* d_in, const int* in_sizes, int n_in,
                              void* d_out, int out_size)
{
    const float* dq = (const float*)d_in[0];
    float* out = (float*)d_out;
    const int n = in_sizes[0] / (SEQ * SEQ);   // 128*12 = 1536

    cudaMemsetAsync(out, 0, sizeof(float));
    blob_loss_kernel<<<n, 256>>>(dq, out, 1.0f / (float)n);
}

// round 2
// speedup vs baseline: 1.0031x; 1.0031x over previous
#include <cuda_runtime.h>
#include <math.h>

#define PX 196
#define HS 14
#define SEQ 197
#define BIGL 1000000

__global__ __launch_bounds__(256) void blob_loss_kernel(
    const float* __restrict__ dot_qk,
    float* __restrict__ out,
    float inv_n)
{
    const int bh = blockIdx.x;
    const int t  = threadIdx.x;

    __shared__ float sx[PX];
    __shared__ float xv[PX];
    __shared__ float pu[PX];
    __shared__ int   lab[PX];
    __shared__ float red[256];
    __shared__ int   changed;
    __shared__ float s_mean, s_B;

    // ---- load: 196 contiguous floats at row 0, cols 1..196 of this (b,h) slab
    const float* rowp = dot_qk + (size_t)bh * (SEQ * SEQ) + 1;
    if (t < PX) sx[t] = rowp[t];
    __syncthreads();

    // ---- mean over 196
    float v = (t < PX) ? sx[t] : 0.0f;
    red[t] = v;
    __syncthreads();
    #pragma unroll
    for (int s = 128; s > 0; s >>= 1) {
        if (t < s) red[t] += red[t + s];
        __syncthreads();
    }
    if (t == 0) s_mean = red[0] * (1.0f / (float)PX);
    __syncthreads();
    const float m = s_mean;

    // ---- mask, xv, init labels
    bool  msk = false;
    float xvv = 0.0f;
    if (t < PX) {
        float x = sx[t];
        msk = (x > m);
        xvv = fmaxf(x - m, 0.0f) + 1e-9f;
        xv[t]  = xvv;
        lab[t] = msk ? t : BIGL;
        pu[t]  = 0.0f;
    }

    // ---- B = sum(xv over mask)
    red[t] = msk ? xvv : 0.0f;
    __syncthreads();
    #pragma unroll
    for (int s = 128; s > 0; s >>= 1) {
        if (t < s) red[t] += red[t + s];
        __syncthreads();
    }
    if (t == 0) s_B = red[0];

    // ---- connected components: min-propagation + pointer jumping to fixpoint
    const int ri = t / HS;
    const int ci = t - ri * HS;

    while (true) {
        __syncthreads();
        if (t == 0) changed = 0;
        __syncthreads();

        int newl = 0;
        if (msk) {
            newl = lab[t];
            #pragma unroll
            for (int di = -1; di <= 1; di++) {
                #pragma unroll
                for (int dj = -1; dj <= 1; dj++) {
                    int rr = ri + di, cc = ci + dj;
                    if (rr >= 0 && rr < HS && cc >= 0 && cc < HS) {
                        int l = lab[rr * HS + cc];
                        newl = min(newl, l);
                    }
                }
            }
            // pointer jumping (labels always index masked pixels; lab[l] <= l)
            newl = lab[newl];
            newl = lab[newl];
        }
        __syncthreads();
        if (msk && newl < lab[t]) {
            lab[t] = newl;
            changed = 1;
        }
        __syncthreads();
        if (!changed) break;
    }

    // ---- per-component sums via shared atomics
    if (msk) atomicAdd(&pu[lab[t]], xv[t]);
    __syncthreads();

    // ---- entropy over component roots
    float h = 0.0f;
    if (t < PX && msk && lab[t] == t) {
        float p = pu[t] / s_B;
        h = -p * logf(p);
    }
    red[t] = h;
    __syncthreads();
    #pragma unroll
    for (int s = 128; s > 0; s >>= 1) {
        if (t < s) red[t] += red[t + s];
        __syncthreads();
    }
    if (t == 0) atomicAdd(out, red[0] * inv_n);
}

extern "C" void kernel_launch(void* const* d_in, const int* in_sizes, int n_in,
                              void* d_out, int out_size)
{
    const float* dq = (const float*)d_in[0];
    float* out = (float*)d_out;
    const int n = in_sizes[0] / (SEQ * SEQ);   // 128*12 = 1536

    cudaMemsetAsync(out, 0, sizeof(float));
    blob_loss_kernel<<<n, 256>>>(dq, out, 1.0f / (float)n);
}